// round 2
// baseline (speedup 1.0000x reference)
#include <cuda_runtime.h>
#include <cstdint>

#define NMAX 100000
#define EMAX 3200000

// Scratch (device globals: allocation-free rule)
__device__ __align__(16) float g_proj[3ull * NMAX * 64];   // [m][n][c]  m: 0=lin 1=src 2=dst
__device__ __align__(16) float g_denom[(size_t)NMAX * 64];
__device__ __align__(16) float g_acc[(size_t)NMAX * 64];
__device__ int g_idx64;

// ---------------------------------------------------------------------------
// Zero denom + acc
// ---------------------------------------------------------------------------
__global__ void zero_kernel(int count4) {
    int i = blockIdx.x * blockDim.x + threadIdx.x;
    float4 z = make_float4(0.f, 0.f, 0.f, 0.f);
    if (i < count4) {
        ((float4*)g_denom)[i] = z;
        ((float4*)g_acc)[i] = z;
    }
}

// ---------------------------------------------------------------------------
// Detect whether edge_index is int64 (high 32-bit words all zero) or int32
// ---------------------------------------------------------------------------
__global__ void detect_kernel(const int* __restrict__ ei) {
    if (threadIdx.x == 0 && blockIdx.x == 0) {
        int is64 = 1;
        for (int i = 1; i < 256; i += 2) {
            if (ei[i] != 0) { is64 = 0; break; }
        }
        g_idx64 = is64;
    }
}

// ---------------------------------------------------------------------------
// Node projections: g_proj[m][n][c] = sum_j x[n][j] * Wm[h][j][k], c = h*16+k
// block = 192 threads (one per (m,c)); each block handles 64 nodes.
// Weight column kept in registers; x rows broadcast from shared.
// ---------------------------------------------------------------------------
__global__ __launch_bounds__(192) void proj_kernel(
    const float* __restrict__ x,
    const float* __restrict__ W_lin,
    const float* __restrict__ W_src,
    const float* __restrict__ W_dst,
    int N)
{
    const int c2 = threadIdx.x;        // 0..191
    const int m  = c2 >> 6;            // which matrix
    const int c  = c2 & 63;
    const int h  = c >> 4;
    const int k  = c & 15;
    const float* W = (m == 0) ? W_lin : ((m == 1) ? W_src : W_dst);

    float w[64];
#pragma unroll
    for (int j = 0; j < 64; j++) w[j] = __ldg(&W[h * 1024 + j * 16 + k]);

    __shared__ float4 sx4[4][16];      // 4 node rows of 64 floats

    const int base = blockIdx.x * 64;
    float* outp = g_proj + (size_t)m * N * 64;

    for (int nb = 0; nb < 64; nb += 4) {
        __syncthreads();
        if (threadIdx.x < 64) {
            int row  = threadIdx.x >> 4;
            int col4 = threadIdx.x & 15;
            int node = base + nb + row;
            if (node >= N) node = N - 1;           // clamp (safe read)
            sx4[row][col4] = ((const float4*)x)[(size_t)node * 16 + col4];
        }
        __syncthreads();

        float a0 = 0.f, a1 = 0.f, a2 = 0.f, a3 = 0.f;
#pragma unroll
        for (int j4 = 0; j4 < 16; j4++) {
            float4 v0 = sx4[0][j4];
            float4 v1 = sx4[1][j4];
            float4 v2 = sx4[2][j4];
            float4 v3 = sx4[3][j4];
            int j = j4 * 4;
            a0 = fmaf(v0.x, w[j], a0); a0 = fmaf(v0.y, w[j+1], a0); a0 = fmaf(v0.z, w[j+2], a0); a0 = fmaf(v0.w, w[j+3], a0);
            a1 = fmaf(v1.x, w[j], a1); a1 = fmaf(v1.y, w[j+1], a1); a1 = fmaf(v1.z, w[j+2], a1); a1 = fmaf(v1.w, w[j+3], a1);
            a2 = fmaf(v2.x, w[j], a2); a2 = fmaf(v2.y, w[j+1], a2); a2 = fmaf(v2.z, w[j+2], a2); a2 = fmaf(v2.w, w[j+3], a2);
            a3 = fmaf(v3.x, w[j], a3); a3 = fmaf(v3.y, w[j+1], a3); a3 = fmaf(v3.z, w[j+2], a3); a3 = fmaf(v3.w, w[j+3], a3);
        }
        int n0 = base + nb;
        if (n0 + 0 < N) outp[(size_t)(n0 + 0) * 64 + c] = a0;
        if (n0 + 1 < N) outp[(size_t)(n0 + 1) * 64 + c] = a1;
        if (n0 + 2 < N) outp[(size_t)(n0 + 2) * 64 + c] = a2;
        if (n0 + 3 < N) outp[(size_t)(n0 + 3) * 64 + c] = a3;
    }
}

// ---------------------------------------------------------------------------
// Edge pass: one thread per (edge, head). Computes ex = exp(logit) without
// max-subtraction (logits bounded ~ +-8 by construction) and accumulates
//   denom[dst][c] += ex
//   acc[dst][c]   += ex * (x_lin[src][c] + delta[c])
// with vector global reductions.
// ---------------------------------------------------------------------------
__device__ __forceinline__ void red_add_v4(float* p, float a, float b, float c, float d) {
    asm volatile("red.global.add.v4.f32 [%0], {%1, %2, %3, %4};"
                 :: "l"(p), "f"(a), "f"(b), "f"(c), "f"(d) : "memory");
}

__global__ __launch_bounds__(256) void edge_kernel(
    const void* __restrict__ ei_raw,
    const float* __restrict__ pos,
    const float* __restrict__ W_pos,
    const float* __restrict__ b_pos,
    int N, int E)
{
    __shared__ float sWp[192];   // [h][j][k] = h*48 + j*16 + k
    __shared__ float sbp[64];
    if (threadIdx.x < 192) sWp[threadIdx.x] = W_pos[threadIdx.x];
    if (threadIdx.x < 64)  sbp[threadIdx.x] = b_pos[threadIdx.x];
    __syncthreads();

    long long t = (long long)blockIdx.x * blockDim.x + threadIdx.x;
    if (t >= (long long)E * 4) return;
    const int e = (int)(t >> 2);
    const int h = (int)(t & 3);

    int s, d;
    if (g_idx64) {
        s = (int)((const long long*)ei_raw)[e];
        d = (int)((const long long*)ei_raw)[(size_t)E + e];
    } else {
        s = ((const int*)ei_raw)[e];
        d = ((const int*)ei_raw)[(size_t)E + e];
    }

    const float rx = pos[3 * s + 0] - pos[3 * d + 0];
    const float ry = pos[3 * s + 1] - pos[3 * d + 1];
    const float rz = pos[3 * s + 2] - pos[3 * d + 2];

    const float4* plin = (const float4*)(g_proj + (size_t)s * 64 + h * 16);
    const float4* psrc = (const float4*)(g_proj + (size_t)N * 64 + (size_t)s * 64 + h * 16);
    const float4* pdst = (const float4*)(g_proj + 2ull * N * 64 + (size_t)d * 64 + h * 16);

    const float* wp0 = sWp + h * 48;
    const float* wp1 = wp0 + 16;
    const float* wp2 = wp0 + 32;
    const float* bp  = sbp + h * 16;

    float* dden = g_denom + (size_t)d * 64 + h * 16;
    float* dacc = g_acc   + (size_t)d * 64 + h * 16;

#pragma unroll
    for (int k4 = 0; k4 < 4; k4++) {
        float4 vl = plin[k4];
        float4 vs = psrc[k4];
        float4 vd = pdst[k4];
        int k = k4 * 4;

        float dl0 = fmaf(rx, wp0[k+0], fmaf(ry, wp1[k+0], fmaf(rz, wp2[k+0], bp[k+0])));
        float dl1 = fmaf(rx, wp0[k+1], fmaf(ry, wp1[k+1], fmaf(rz, wp2[k+1], bp[k+1])));
        float dl2 = fmaf(rx, wp0[k+2], fmaf(ry, wp1[k+2], fmaf(rz, wp2[k+2], bp[k+2])));
        float dl3 = fmaf(rx, wp0[k+3], fmaf(ry, wp1[k+3], fmaf(rz, wp2[k+3], bp[k+3])));

        float e0 = __expf(vs.x - vd.x + dl0);
        float e1 = __expf(vs.y - vd.y + dl1);
        float e2 = __expf(vs.z - vd.z + dl2);
        float e3 = __expf(vs.w - vd.w + dl3);

        float n0 = e0 * (vl.x + dl0);
        float n1 = e1 * (vl.y + dl1);
        float n2 = e2 * (vl.z + dl2);
        float n3 = e3 * (vl.w + dl3);

        red_add_v4(dden + k, e0, e1, e2, e3);
        red_add_v4(dacc + k, n0, n1, n2, n3);
    }
}

// ---------------------------------------------------------------------------
// Finalize: y = acc/denom, then MLP  out = relu(y@W1+b1)@W2+b2
// block = 256 threads = 4 nodes x 64 channels
// ---------------------------------------------------------------------------
__global__ __launch_bounds__(256) void mlp_kernel(
    const float* __restrict__ W1, const float* __restrict__ b1,
    const float* __restrict__ W2, const float* __restrict__ b2,
    float* __restrict__ out, int N)
{
    __shared__ float sW1[64 * 64];
    __shared__ float sW2[64 * 64];
    __shared__ float sy[4][64];
    __shared__ float sh[4][64];

    for (int i = threadIdx.x; i < 4096; i += 256) {
        sW1[i] = W1[i];
        sW2[i] = W2[i];
    }

    const int i = threadIdx.x >> 6;   // node within block
    const int o = threadIdx.x & 63;   // channel
    const int n = blockIdx.x * 4 + i;

    float yv = 0.f;
    if (n < N) {
        float den = g_denom[(size_t)n * 64 + o];
        float acc = g_acc[(size_t)n * 64 + o];
        yv = acc / (den + 1e-16f);
    }
    sy[i][o] = yv;
    __syncthreads();

    float a = b1[o];
#pragma unroll
    for (int c = 0; c < 64; c++) a = fmaf(sy[i][c], sW1[c * 64 + o], a);
    sh[i][o] = fmaxf(a, 0.f);
    __syncthreads();

    float r = b2[o];
#pragma unroll
    for (int c = 0; c < 64; c++) r = fmaf(sh[i][c], sW2[c * 64 + o], r);
    if (n < N) out[(size_t)n * 64 + o] = r;
}

// ---------------------------------------------------------------------------
extern "C" void kernel_launch(void* const* d_in, const int* in_sizes, int n_in,
                              void* d_out, int out_size) {
    const float* x     = (const float*)d_in[0];
    const float* pos   = (const float*)d_in[1];
    const void*  ei    = d_in[2];
    const float* W_lin = (const float*)d_in[3];
    const float* W_src = (const float*)d_in[4];
    const float* W_dst = (const float*)d_in[5];
    const float* W_pos = (const float*)d_in[6];
    const float* b_pos = (const float*)d_in[7];
    const float* W1    = (const float*)d_in[8];
    const float* b1    = (const float*)d_in[9];
    const float* W2    = (const float*)d_in[10];
    const float* b2    = (const float*)d_in[11];
    float* out = (float*)d_out;

    const int N = in_sizes[0] / 64;
    const int E = in_sizes[2] / 2;

    // zero accumulators (N*64*2 floats -> N*32 float4, writing both arrays)
    {
        int count4 = N * 16;
        zero_kernel<<<(count4 + 255) / 256, 256>>>(count4);
    }
    detect_kernel<<<1, 32>>>((const int*)ei);
    proj_kernel<<<(N + 63) / 64, 192>>>(x, W_lin, W_src, W_dst, N);
    {
        long long total = (long long)E * 4;
        int blocks = (int)((total + 255) / 256);
        edge_kernel<<<blocks, 256>>>(ei, pos, W_pos, b_pos, N, E);
    }
    mlp_kernel<<<(N + 3) / 4, 256>>>(W1, b1, W2, b2, out, N);
}

// round 3
// speedup vs baseline: 2.2192x; 2.2192x over previous
#include <cuda_runtime.h>
#include <cstdint>

#define NMAX 100000
#define EMAX 3200000
#define SCAN_BLK 1024

// ---------------- device scratch ----------------
__device__ __align__(16) float g_proj[(size_t)NMAX * 128];   // [n][0..63]=x_lin, [64..127]=a_src
__device__ __align__(16) float g_y[(size_t)NMAX * 64];       // attention output per node
__device__ int g_count[NMAX];
__device__ int g_incl[NMAX];        // inclusive scan within block
__device__ int g_offset[NMAX + 1];  // CSR offsets
__device__ int g_cursor[NMAX];      // scatter cursors
__device__ int g_bsum[128];
__device__ int g_bpre[128];
__device__ int g_esrc[EMAX];        // src node id sorted by dst
__device__ int g_idx64;

// ---------------- detect edge_index dtype ----------------
__global__ void detect_kernel(const int* __restrict__ ei) {
    if (threadIdx.x == 0) {
        int is64 = 1;
        for (int i = 1; i < 256; i += 2)
            if (ei[i] != 0) { is64 = 0; break; }
        g_idx64 = is64;
    }
}

// ---------------- zero histogram ----------------
__global__ void zero_kernel(int N) {
    int i = blockIdx.x * blockDim.x + threadIdx.x;
    if (i < N) g_count[i] = 0;
}

// ---------------- histogram of dst ----------------
__global__ __launch_bounds__(256) void hist_kernel(const void* __restrict__ ei, int E) {
    int t = blockIdx.x * blockDim.x + threadIdx.x;
    if (t >= E) return;
    int d;
    if (g_idx64) d = (int)((const long long*)ei)[(size_t)E + t];
    else         d = ((const int*)ei)[(size_t)E + t];
    atomicAdd(&g_count[d], 1);
}

// ---------------- scan phase 1: per-block inclusive scan ----------------
__global__ __launch_bounds__(SCAN_BLK) void scan1_kernel(int N) {
    __shared__ int sh[SCAN_BLK];
    int tid = threadIdx.x;
    int i = blockIdx.x * SCAN_BLK + tid;
    int v = (i < N) ? g_count[i] : 0;
    sh[tid] = v;
    __syncthreads();
#pragma unroll
    for (int ofs = 1; ofs < SCAN_BLK; ofs <<= 1) {
        int t = (tid >= ofs) ? sh[tid - ofs] : 0;
        __syncthreads();
        sh[tid] += t;
        __syncthreads();
    }
    if (i < N) g_incl[i] = sh[tid];
    if (tid == SCAN_BLK - 1) g_bsum[blockIdx.x] = sh[tid];
}

// ---------------- scan phase 2: scan of block sums (<=128 blocks) ----------------
__global__ void scan2_kernel(int nb) {
    __shared__ int sh[128];
    int tid = threadIdx.x;
    sh[tid] = (tid < nb) ? g_bsum[tid] : 0;
    __syncthreads();
#pragma unroll
    for (int ofs = 1; ofs < 128; ofs <<= 1) {
        int t = (tid >= ofs) ? sh[tid - ofs] : 0;
        __syncthreads();
        sh[tid] += t;
        __syncthreads();
    }
    if (tid < nb) g_bpre[tid] = sh[tid] - g_bsum[tid];   // exclusive
}

// ---------------- scan phase 3: final offsets + cursors ----------------
__global__ void scan3_kernel(int N, int E) {
    int i = blockIdx.x * blockDim.x + threadIdx.x;
    if (i < N) {
        int off = g_bpre[i / SCAN_BLK] + g_incl[i] - g_count[i];
        g_offset[i] = off;
        g_cursor[i] = off;
    }
    if (i == 0) g_offset[N] = E;
}

// ---------------- scatter: sort src ids by dst ----------------
__global__ __launch_bounds__(256) void scatter_kernel(const void* __restrict__ ei, int E) {
    int t = blockIdx.x * blockDim.x + threadIdx.x;
    if (t >= E) return;
    int s, d;
    if (g_idx64) {
        s = (int)((const long long*)ei)[t];
        d = (int)((const long long*)ei)[(size_t)E + t];
    } else {
        s = ((const int*)ei)[t];
        d = ((const int*)ei)[(size_t)E + t];
    }
    int idx = atomicAdd(&g_cursor[d], 1);
    g_esrc[idx] = s;
}

// ---------------- node projections ----------------
// g_proj[n][c]: c<64 -> x@W_lin ; c>=64 -> x@W_src.  64 nodes/block, 128 threads.
#define SX_STRIDE 68
__global__ __launch_bounds__(128) void proj_kernel(
    const float* __restrict__ x,
    const float* __restrict__ W_lin,
    const float* __restrict__ W_src,
    int N)
{
    const int c  = threadIdx.x;        // 0..127
    const int m  = c >> 6;
    const int cc = c & 63;
    const int h  = cc >> 4;
    const int k  = cc & 15;
    const float* W = m ? W_src : W_lin;

    float w[64];
#pragma unroll
    for (int j = 0; j < 64; j++) w[j] = __ldg(&W[h * 1024 + j * 16 + k]);

    __shared__ float sx[64 * SX_STRIDE];   // transposed: sx[j][node], stride 68

    const int base = blockIdx.x * 64;
    // load x tile transposed: thread reads float4s coalesced
    for (int f = threadIdx.x; f < 64 * 16; f += 128) {
        int node = f >> 4;
        int j4 = f & 15;
        int gn = base + node;
        if (gn >= N) gn = N - 1;
        float4 v = ((const float4*)x)[(size_t)gn * 16 + j4];
        int j = j4 * 4;
        sx[(j + 0) * SX_STRIDE + node] = v.x;
        sx[(j + 1) * SX_STRIDE + node] = v.y;
        sx[(j + 2) * SX_STRIDE + node] = v.z;
        sx[(j + 3) * SX_STRIDE + node] = v.w;
    }
    __syncthreads();

#pragma unroll
    for (int p = 0; p < 2; p++) {
        float acc[32];
#pragma unroll
        for (int r = 0; r < 32; r++) acc[r] = 0.f;
        for (int j = 0; j < 64; j++) {
            const float4* row = (const float4*)(sx + j * SX_STRIDE + p * 32);
            float wj = w[j];
#pragma unroll
            for (int q = 0; q < 8; q++) {
                float4 v = row[q];
                acc[q * 4 + 0] = fmaf(v.x, wj, acc[q * 4 + 0]);
                acc[q * 4 + 1] = fmaf(v.y, wj, acc[q * 4 + 1]);
                acc[q * 4 + 2] = fmaf(v.z, wj, acc[q * 4 + 2]);
                acc[q * 4 + 3] = fmaf(v.w, wj, acc[q * 4 + 3]);
            }
        }
#pragma unroll
        for (int r = 0; r < 32; r++) {
            int gn = base + p * 32 + r;
            if (gn < N) g_proj[(size_t)gn * 128 + c] = acc[r];
        }
    }
}

// ---------------- per-destination-node attention ----------------
// One block (4 warps, 128 threads) per node. Lane owns channels 2l, 2l+1.
__global__ __launch_bounds__(128) void node_kernel(
    const float* __restrict__ pos,
    const float* __restrict__ W_pos,
    const float* __restrict__ b_pos,
    int N)
{
    const int n = blockIdx.x;
    const int tid = threadIdx.x;
    const int w = tid >> 5;
    const int l = tid & 31;
    const int c0 = 2 * l;
    const int c1 = c0 + 1;
    const int h = c0 >> 4;
    const int k0 = c0 & 15;
    const int k1 = c1 & 15;

    const float w00 = __ldg(&W_pos[h * 48 + 0 * 16 + k0]);
    const float w10 = __ldg(&W_pos[h * 48 + 1 * 16 + k0]);
    const float w20 = __ldg(&W_pos[h * 48 + 2 * 16 + k0]);
    const float b0  = __ldg(&b_pos[h * 16 + k0]);
    const float w01 = __ldg(&W_pos[h * 48 + 0 * 16 + k1]);
    const float w11 = __ldg(&W_pos[h * 48 + 1 * 16 + k1]);
    const float w21 = __ldg(&W_pos[h * 48 + 2 * 16 + k1]);
    const float b1  = __ldg(&b_pos[h * 16 + k1]);

    const float px = __ldg(&pos[3 * n + 0]);
    const float py = __ldg(&pos[3 * n + 1]);
    const float pz = __ldg(&pos[3 * n + 2]);

    const int off = g_offset[n];
    const int end = g_offset[n + 1];

    float den0 = 0.f, den1 = 0.f, ac0 = 0.f, ac1 = 0.f;

    int e = off + w;
    int sN = (e < end) ? g_esrc[e] : 0;
    while (e < end) {
        int s = sN;
        int e2 = e + 4;
        if (e2 < end) sN = g_esrc[e2];     // prefetch next src id

        float rx = __ldg(&pos[3 * s + 0]) - px;
        float ry = __ldg(&pos[3 * s + 1]) - py;
        float rz = __ldg(&pos[3 * s + 2]) - pz;

        const float* rowp = g_proj + (size_t)s * 128;
        float2 vl = *(const float2*)(rowp + c0);        // x_lin
        float2 va = *(const float2*)(rowp + 64 + c0);   // a_src

        float d0 = fmaf(rx, w00, fmaf(ry, w10, fmaf(rz, w20, b0)));
        float d1 = fmaf(rx, w01, fmaf(ry, w11, fmaf(rz, w21, b1)));

        float e0 = __expf(va.x + d0);
        float e1 = __expf(va.y + d1);

        den0 += e0; den1 += e1;
        ac0 = fmaf(e0, vl.x + d0, ac0);
        ac1 = fmaf(e1, vl.y + d1, ac1);

        e = e2;
    }

    __shared__ float sden[4][64];
    __shared__ float sacc[4][64];
    sden[w][c0] = den0; sden[w][c1] = den1;
    sacc[w][c0] = ac0;  sacc[w][c1] = ac1;
    __syncthreads();

    if (tid < 64) {
        float D = sden[0][tid] + sden[1][tid] + sden[2][tid] + sden[3][tid];
        float A = sacc[0][tid] + sacc[1][tid] + sacc[2][tid] + sacc[3][tid];
        g_y[(size_t)n * 64 + tid] = A / (D + 1e-16f);
    }
}

// ---------------- MLP: out = relu(y@W1+b1)@W2+b2, 64 nodes/block ----------------
__global__ __launch_bounds__(256) void mlp_kernel(
    const float* __restrict__ W1, const float* __restrict__ b1,
    const float* __restrict__ W2, const float* __restrict__ b2,
    float* __restrict__ out, int N)
{
    __shared__ float sW1[4096];
    __shared__ float sW2[4096];
    __shared__ float sy[4][64];
    __shared__ float sh_[4][64];

    for (int i = threadIdx.x; i < 4096; i += 256) {
        sW1[i] = W1[i];
        sW2[i] = W2[i];
    }

    const int i = threadIdx.x >> 6;
    const int o = threadIdx.x & 63;
    const float B1 = __ldg(&b1[o]);
    const float B2 = __ldg(&b2[o]);
    __syncthreads();

    for (int g = 0; g < 16; g++) {
        int n = blockIdx.x * 64 + g * 4 + i;
        float yv = (n < N) ? g_y[(size_t)n * 64 + o] : 0.f;
        sy[i][o] = yv;
        __syncthreads();

        float a = B1;
#pragma unroll
        for (int ci = 0; ci < 64; ci++) a = fmaf(sy[i][ci], sW1[ci * 64 + o], a);
        sh_[i][o] = fmaxf(a, 0.f);
        __syncthreads();

        float r = B2;
#pragma unroll
        for (int ci = 0; ci < 64; ci++) r = fmaf(sh_[i][ci], sW2[ci * 64 + o], r);
        if (n < N) out[(size_t)n * 64 + o] = r;
        __syncthreads();
    }
}

// ---------------- host ----------------
extern "C" void kernel_launch(void* const* d_in, const int* in_sizes, int n_in,
                              void* d_out, int out_size) {
    const float* x     = (const float*)d_in[0];
    const float* pos   = (const float*)d_in[1];
    const void*  ei    = d_in[2];
    const float* W_lin = (const float*)d_in[3];
    const float* W_src = (const float*)d_in[4];
    // d_in[5] = W_dst (unused: cancels in softmax)
    const float* W_pos = (const float*)d_in[6];
    const float* b_pos = (const float*)d_in[7];
    const float* W1    = (const float*)d_in[8];
    const float* b1    = (const float*)d_in[9];
    const float* W2    = (const float*)d_in[10];
    const float* b2    = (const float*)d_in[11];
    float* out = (float*)d_out;

    const int N = in_sizes[0] / 64;
    const int E = in_sizes[2] / 2;
    const int nb = (N + SCAN_BLK - 1) / SCAN_BLK;

    detect_kernel<<<1, 32>>>((const int*)ei);
    zero_kernel<<<(N + 1023) / 1024, 1024>>>(N);
    hist_kernel<<<(E + 255) / 256, 256>>>(ei, E);
    scan1_kernel<<<nb, SCAN_BLK>>>(N);
    scan2_kernel<<<1, 128>>>(nb);
    scan3_kernel<<<(N + 255) / 256, 256>>>(N, E);
    scatter_kernel<<<(E + 255) / 256, 256>>>(ei, E);
    proj_kernel<<<(N + 63) / 64, 128>>>(x, W_lin, W_src, N);
    node_kernel<<<N, 128>>>(pos, W_pos, b_pos, N);
    mlp_kernel<<<(N + 63) / 64, 256>>>(W1, b1, W2, b2, out, N);
}

// round 4
// speedup vs baseline: 2.3763x; 1.0708x over previous
#include <cuda_runtime.h>
#include <cstdint>

#define NMAX 100000
#define EMAX 3200000
#define SCAN_BLK 1024

// ---------------- device scratch ----------------
__device__ __align__(16) float  g_proj[(size_t)NMAX * 128]; // [n][4l+{0,1}]=lin[2l,2l+1], [4l+{2,3}]=asrc[2l,2l+1]
__device__ __align__(16) float  g_y[(size_t)NMAX * 64];
__device__ __align__(16) float4 g_pos4[NMAX];
__device__ int g_count[NMAX];
__device__ int g_incl[NMAX];
__device__ int g_offset[NMAX + 1];
__device__ int g_cursor[NMAX];
__device__ int g_bsum[128];
__device__ int g_bpre[128];
__device__ int g_esrc[EMAX];
__device__ int g_idx64;

// ---------------- detect edge_index dtype ----------------
__global__ void detect_kernel(const int* __restrict__ ei) {
    if (threadIdx.x == 0) {
        int is64 = 1;
        for (int i = 1; i < 256; i += 2)
            if (ei[i] != 0) { is64 = 0; break; }
        g_idx64 = is64;
    }
}

// ---------------- zero histogram + pad pos ----------------
__global__ void prep_kernel(const float* __restrict__ pos, int N) {
    int i = blockIdx.x * blockDim.x + threadIdx.x;
    if (i < N) {
        g_count[i] = 0;
        g_pos4[i] = make_float4(pos[3 * i + 0], pos[3 * i + 1], pos[3 * i + 2], 0.f);
    }
}

// ---------------- histogram of dst ----------------
__global__ __launch_bounds__(256) void hist_kernel(const void* __restrict__ ei, int E) {
    int t = blockIdx.x * blockDim.x + threadIdx.x;
    if (t >= E) return;
    int d;
    if (g_idx64) d = (int)((const long long*)ei)[(size_t)E + t];
    else         d = ((const int*)ei)[(size_t)E + t];
    atomicAdd(&g_count[d], 1);
}

// ---------------- scan phase 1 ----------------
__global__ __launch_bounds__(SCAN_BLK) void scan1_kernel(int N) {
    __shared__ int sh[SCAN_BLK];
    int tid = threadIdx.x;
    int i = blockIdx.x * SCAN_BLK + tid;
    int v = (i < N) ? g_count[i] : 0;
    sh[tid] = v;
    __syncthreads();
#pragma unroll
    for (int ofs = 1; ofs < SCAN_BLK; ofs <<= 1) {
        int t = (tid >= ofs) ? sh[tid - ofs] : 0;
        __syncthreads();
        sh[tid] += t;
        __syncthreads();
    }
    if (i < N) g_incl[i] = sh[tid];
    if (tid == SCAN_BLK - 1) g_bsum[blockIdx.x] = sh[tid];
}

// ---------------- scan phase 2 ----------------
__global__ void scan2_kernel(int nb) {
    __shared__ int sh[128];
    int tid = threadIdx.x;
    sh[tid] = (tid < nb) ? g_bsum[tid] : 0;
    __syncthreads();
#pragma unroll
    for (int ofs = 1; ofs < 128; ofs <<= 1) {
        int t = (tid >= ofs) ? sh[tid - ofs] : 0;
        __syncthreads();
        sh[tid] += t;
        __syncthreads();
    }
    if (tid < nb) g_bpre[tid] = sh[tid] - g_bsum[tid];
}

// ---------------- scan phase 3 ----------------
__global__ void scan3_kernel(int N, int E) {
    int i = blockIdx.x * blockDim.x + threadIdx.x;
    if (i < N) {
        int off = g_bpre[i / SCAN_BLK] + g_incl[i] - g_count[i];
        g_offset[i] = off;
        g_cursor[i] = off;
    }
    if (i == 0) g_offset[N] = E;
}

// ---------------- scatter: sort src ids by dst ----------------
__global__ __launch_bounds__(256) void scatter_kernel(const void* __restrict__ ei, int E) {
    int t = blockIdx.x * blockDim.x + threadIdx.x;
    if (t >= E) return;
    int s, d;
    if (g_idx64) {
        s = (int)((const long long*)ei)[t];
        d = (int)((const long long*)ei)[(size_t)E + t];
    } else {
        s = ((const int*)ei)[t];
        d = ((const int*)ei)[(size_t)E + t];
    }
    int idx = atomicAdd(&g_cursor[d], 1);
    g_esrc[idx] = s;
}

// ---------------- node projections ----------------
// 64 nodes/block, 128 threads; thread = (matrix m, channel cc).
// Output interleaved: row[4*(cc>>1) + (cc&1) + 2*m]
#define SX_STRIDE 68
__global__ __launch_bounds__(128) void proj_kernel(
    const float* __restrict__ x,
    const float* __restrict__ W_lin,
    const float* __restrict__ W_src,
    int N)
{
    const int c  = threadIdx.x;
    const int m  = c >> 6;
    const int cc = c & 63;
    const int h  = cc >> 4;
    const int k  = cc & 15;
    const int outcol = 4 * (cc >> 1) + (cc & 1) + 2 * m;
    const float* W = m ? W_src : W_lin;

    float w[64];
#pragma unroll
    for (int j = 0; j < 64; j++) w[j] = __ldg(&W[h * 1024 + j * 16 + k]);

    __shared__ float sx[64 * SX_STRIDE];

    const int base = blockIdx.x * 64;
    for (int f = threadIdx.x; f < 64 * 16; f += 128) {
        int node = f >> 4;
        int j4 = f & 15;
        int gn = base + node;
        if (gn >= N) gn = N - 1;
        float4 v = ((const float4*)x)[(size_t)gn * 16 + j4];
        int j = j4 * 4;
        sx[(j + 0) * SX_STRIDE + node] = v.x;
        sx[(j + 1) * SX_STRIDE + node] = v.y;
        sx[(j + 2) * SX_STRIDE + node] = v.z;
        sx[(j + 3) * SX_STRIDE + node] = v.w;
    }
    __syncthreads();

#pragma unroll
    for (int p = 0; p < 2; p++) {
        float acc[32];
#pragma unroll
        for (int r = 0; r < 32; r++) acc[r] = 0.f;
        for (int j = 0; j < 64; j++) {
            const float4* row = (const float4*)(sx + j * SX_STRIDE + p * 32);
            float wj = w[j];
#pragma unroll
            for (int q = 0; q < 8; q++) {
                float4 v = row[q];
                acc[q * 4 + 0] = fmaf(v.x, wj, acc[q * 4 + 0]);
                acc[q * 4 + 1] = fmaf(v.y, wj, acc[q * 4 + 1]);
                acc[q * 4 + 2] = fmaf(v.z, wj, acc[q * 4 + 2]);
                acc[q * 4 + 3] = fmaf(v.w, wj, acc[q * 4 + 3]);
            }
        }
#pragma unroll
        for (int r = 0; r < 32; r++) {
            int gn = base + p * 32 + r;
            if (gn < N) g_proj[(size_t)gn * 128 + outcol] = acc[r];
        }
    }
}

// ---------------- per-destination-node attention: warp per node ----------------
__global__ __launch_bounds__(256) void node_kernel(
    const float* __restrict__ W_pos,
    const float* __restrict__ b_pos,
    int N)
{
    const int warp = threadIdx.x >> 5;
    const int l = threadIdx.x & 31;
    const int n = blockIdx.x * 8 + warp;
    if (n >= N) return;

    const int c0 = 2 * l;
    const int h  = c0 >> 4;
    const int k0 = c0 & 15;
    const int k1 = k0 + 1;

    const float w00 = __ldg(&W_pos[h * 48 + 0  + k0]);
    const float w10 = __ldg(&W_pos[h * 48 + 16 + k0]);
    const float w20 = __ldg(&W_pos[h * 48 + 32 + k0]);
    const float b0  = __ldg(&b_pos[h * 16 + k0]);
    const float w01 = __ldg(&W_pos[h * 48 + 0  + k1]);
    const float w11 = __ldg(&W_pos[h * 48 + 16 + k1]);
    const float w21 = __ldg(&W_pos[h * 48 + 32 + k1]);
    const float b1  = __ldg(&b_pos[h * 16 + k1]);

    const float4 pn = g_pos4[n];
    const int off = g_offset[n];
    const int end = g_offset[n + 1];

    float den0 = 0.f, den1 = 0.f, ac0 = 0.f, ac1 = 0.f;

    for (int base = off; base < end; base += 32) {
        int idx = base + l;
        int sid = (idx < end) ? g_esrc[idx] : 0;
        int cnt = min(32, end - base);
#pragma unroll 4
        for (int j = 0; j < cnt; j++) {
            int s = __shfl_sync(0xffffffffu, sid, j);
            float4 p = __ldg(&g_pos4[s]);
            float4 v = __ldg((const float4*)(g_proj + (size_t)s * 128 + 4 * l));
            float rx = p.x - pn.x;
            float ry = p.y - pn.y;
            float rz = p.z - pn.z;

            float d0 = fmaf(rx, w00, fmaf(ry, w10, fmaf(rz, w20, b0)));
            float d1 = fmaf(rx, w01, fmaf(ry, w11, fmaf(rz, w21, b1)));

            float e0 = __expf(v.z + d0);
            float e1 = __expf(v.w + d1);

            den0 += e0;
            den1 += e1;
            ac0 = fmaf(e0, v.x + d0, ac0);
            ac1 = fmaf(e1, v.y + d1, ac1);
        }
    }

    float2 r;
    r.x = ac0 / (den0 + 1e-16f);
    r.y = ac1 / (den1 + 1e-16f);
    ((float2*)g_y)[(size_t)n * 32 + l] = r;
}

// ---------------- MLP: out = relu(y@W1+b1)@W2+b2, 64 nodes/block ----------------
__global__ __launch_bounds__(256) void mlp_kernel(
    const float* __restrict__ W1, const float* __restrict__ b1,
    const float* __restrict__ W2, const float* __restrict__ b2,
    float* __restrict__ out, int N)
{
    __shared__ float sW1[4096];
    __shared__ float sW2[4096];
    __shared__ float sy[4][64];
    __shared__ float sh_[4][64];

    for (int i = threadIdx.x; i < 4096; i += 256) {
        sW1[i] = W1[i];
        sW2[i] = W2[i];
    }

    const int i = threadIdx.x >> 6;
    const int o = threadIdx.x & 63;
    const float B1 = __ldg(&b1[o]);
    const float B2 = __ldg(&b2[o]);
    __syncthreads();

    for (int g = 0; g < 16; g++) {
        int n = blockIdx.x * 64 + g * 4 + i;
        float yv = (n < N) ? g_y[(size_t)n * 64 + o] : 0.f;
        sy[i][o] = yv;
        __syncthreads();

        float a = B1;
#pragma unroll
        for (int ci = 0; ci < 64; ci++) a = fmaf(sy[i][ci], sW1[ci * 64 + o], a);
        sh_[i][o] = fmaxf(a, 0.f);
        __syncthreads();

        float r = B2;
#pragma unroll
        for (int ci = 0; ci < 64; ci++) r = fmaf(sh_[i][ci], sW2[ci * 64 + o], r);
        if (n < N) out[(size_t)n * 64 + o] = r;
        __syncthreads();
    }
}

// ---------------- host ----------------
extern "C" void kernel_launch(void* const* d_in, const int* in_sizes, int n_in,
                              void* d_out, int out_size) {
    const float* x     = (const float*)d_in[0];
    const float* pos   = (const float*)d_in[1];
    const void*  ei    = d_in[2];
    const float* W_lin = (const float*)d_in[3];
    const float* W_src = (const float*)d_in[4];
    // d_in[5] = W_dst (cancels in the per-dst softmax)
    const float* W_pos = (const float*)d_in[6];
    const float* b_pos = (const float*)d_in[7];
    const float* W1    = (const float*)d_in[8];
    const float* b1    = (const float*)d_in[9];
    const float* W2    = (const float*)d_in[10];
    const float* b2    = (const float*)d_in[11];
    float* out = (float*)d_out;

    const int N = in_sizes[0] / 64;
    const int E = in_sizes[2] / 2;
    const int nb = (N + SCAN_BLK - 1) / SCAN_BLK;

    detect_kernel<<<1, 32>>>((const int*)ei);
    prep_kernel<<<(N + 255) / 256, 256>>>(pos, N);
    hist_kernel<<<(E + 255) / 256, 256>>>(ei, E);
    scan1_kernel<<<nb, SCAN_BLK>>>(N);
    scan2_kernel<<<1, 128>>>(nb);
    scan3_kernel<<<(N + 255) / 256, 256>>>(N, E);
    scatter_kernel<<<(E + 255) / 256, 256>>>(ei, E);
    proj_kernel<<<(N + 63) / 64, 128>>>(x, W_lin, W_src, N);
    node_kernel<<<(N + 7) / 8, 256>>>(W_pos, b_pos, N);
    mlp_kernel<<<(N + 63) / 64, 256>>>(W1, b1, W2, b2, out, N);
}